// round 5
// baseline (speedup 1.0000x reference)
#include <cuda_runtime.h>
#include <cuda_fp16.h>
#include <math.h>
#include <stdint.h>

#define Bc 4
#define Sc 1024
#define Hc 16
#define Dc 64
#define Tc 2048
#define BM 64
#define BN 64
#define STH 72   // smem row stride in halves: 144B rows, 16B-aligned, ldmatrix conflict-free

// Q pre-scale: ATT_SCALE * log2(e), so softmax uses raw ex2.approx.
#define QSCALE 0.18033688011112042f

// Scratch (static device globals: allowed; no allocation).
__device__ __half g_qh[Bc*Hc*Sc*Dc];
__device__ __half g_kh[Bc*Hc*Sc*Dc];
__device__ __half g_vh[Bc*Hc*Sc*Dc];

__device__ __forceinline__ void ldsm4(uint32_t (&r)[4], const __half* p) {
    uint32_t a = (uint32_t)__cvta_generic_to_shared(p);
    asm volatile("ldmatrix.sync.aligned.m8n8.x4.shared.b16 {%0,%1,%2,%3}, [%4];"
                 : "=r"(r[0]), "=r"(r[1]), "=r"(r[2]), "=r"(r[3]) : "r"(a));
}
__device__ __forceinline__ void ldsm4t(uint32_t (&r)[4], const __half* p) {
    uint32_t a = (uint32_t)__cvta_generic_to_shared(p);
    asm volatile("ldmatrix.sync.aligned.m8n8.x4.trans.shared.b16 {%0,%1,%2,%3}, [%4];"
                 : "=r"(r[0]), "=r"(r[1]), "=r"(r[2]), "=r"(r[3]) : "r"(a));
}
__device__ __forceinline__ void mma16(float (&d)[4], const uint32_t (&a)[4],
                                      uint32_t b0, uint32_t b1) {
    asm volatile("mma.sync.aligned.m16n8k16.row.col.f32.f16.f16.f32 "
                 "{%0,%1,%2,%3},{%4,%5,%6,%7},{%8,%9},{%0,%1,%2,%3};"
                 : "+f"(d[0]), "+f"(d[1]), "+f"(d[2]), "+f"(d[3])
                 : "r"(a[0]), "r"(a[1]), "r"(a[2]), "r"(a[3]), "r"(b0), "r"(b1));
}
__device__ __forceinline__ uint32_t pack_h2(float x, float y) {
    __half2 h = __floats2half2_rn(x, y);
    return *reinterpret_cast<uint32_t*>(&h);
}
__device__ __forceinline__ float ex2(float x) {
    float r;
    asm("ex2.approx.f32 %0, %1;" : "=f"(r) : "f"(x));
    return r;
}
__device__ __forceinline__ void cp16(uint32_t saddr, const void* g, int src_bytes) {
    asm volatile("cp.async.cg.shared.global [%0], [%1], 16, %2;"
                 :: "r"(saddr), "l"(g), "r"(src_bytes));
}

// ---------------------------------------------------------------------------
// Kernel 1: ragged->padded scatter + RoPE, fp16 outputs, Q pre-scaled by
// 0.125*log2(e). 128-thread blocks; all loads batched for MLP.
// ---------------------------------------------------------------------------
__global__ void __launch_bounds__(128)
prep_kernel(const float* __restrict__ q,
            const float* __restrict__ k,
            const float* __restrict__ v,
            const int*   __restrict__ lens)
{
    int idx = blockIdx.x * 128 + threadIdx.x;
    if (idx >= Tc * 4 * 16) return;
    int d2 = (idx & 15) * 2;       // even d2 in [0,32)
    int hq = (idx >> 4) & 3;       // head quad
    int t  = idx >> 6;

    int off = 0, b = 0, pos = 0;
#pragma unroll
    for (int i = 0; i < Bc; i++) {
        int L = __ldg(&lens[i]);
        if (t >= off) { b = i; pos = t - off; }
        off += L;
    }

    // batch all global loads first (MLP ~24)
    float2 Q1[4], Q2[4], K1[4], K2[4], V1[4], V2[4];
#pragma unroll
    for (int hh = 0; hh < 4; hh++) {
        int src = (t * Hc + hq * 4 + hh) * Dc;
        Q1[hh] = *(const float2*)(q + src + d2);
        Q2[hh] = *(const float2*)(q + src + d2 + 32);
        K1[hh] = *(const float2*)(k + src + d2);
        K2[hh] = *(const float2*)(k + src + d2 + 32);
        V1[hh] = *(const float2*)(v + src + d2);
        V2[hh] = *(const float2*)(v + src + d2 + 32);
    }

    const float LOG2_10000_DIV32 = 0.4152410118609203f;
    float s0, c0, s1, c1;
    sincosf((float)pos * exp2f(-(float)d2 * LOG2_10000_DIV32), &s0, &c0);
    sincosf((float)pos * exp2f(-(float)(d2 + 1) * LOG2_10000_DIV32), &s1, &c1);

#pragma unroll
    for (int hh = 0; hh < 4; hh++) {
        int h = hq * 4 + hh;
        int dst = ((b * Hc + h) * Sc + pos) * Dc;
        *(__half2*)(g_qh + dst + d2) =
            __floats2half2_rn((Q1[hh].x * c0 - Q2[hh].x * s0) * QSCALE,
                              (Q1[hh].y * c1 - Q2[hh].y * s1) * QSCALE);
        *(__half2*)(g_qh + dst + d2 + 32) =
            __floats2half2_rn((Q2[hh].x * c0 + Q1[hh].x * s0) * QSCALE,
                              (Q2[hh].y * c1 + Q1[hh].y * s1) * QSCALE);
        *(__half2*)(g_kh + dst + d2) =
            __floats2half2_rn(K1[hh].x * c0 - K2[hh].x * s0,
                              K1[hh].y * c1 - K2[hh].y * s1);
        *(__half2*)(g_kh + dst + d2 + 32) =
            __floats2half2_rn(K2[hh].x * c0 + K1[hh].x * s0,
                              K2[hh].y * c1 + K1[hh].y * s1);
        *(__half2*)(g_vh + dst + d2)      = __floats2half2_rn(V1[hh].x, V1[hh].y);
        *(__half2*)(g_vh + dst + d2 + 32) = __floats2half2_rn(V2[hh].x, V2[hh].y);
    }
}

// ---------------------------------------------------------------------------
// Kernel 2: causal flash attention, fp16 MMA, ex2-domain softmax (no max),
// cp.async double buffering, per-warp masked-block elision, heavy-first.
// ---------------------------------------------------------------------------
__global__ void __launch_bounds__(128)
attn_kernel(const int* __restrict__ lens, float* __restrict__ out)
{
    int qt = (Sc / BM - 1) - blockIdx.x;   // heavy CTAs first
    int h = blockIdx.y, b = blockIdx.z;
    int len = lens[b];
    int q0 = qt * BM;
    if (q0 >= len) return;

    __shared__ __half Qs[BM * STH];
    __shared__ __half Ks[2][BN * STH];
    __shared__ __half Vs[2][BN * STH];

    const int tid  = threadIdx.x;
    const int lane = tid & 31;
    const int w    = tid >> 5;

    const __half* qb = g_qh + ((size_t)(b * Hc + h) * Sc) * Dc;
    const __half* kb = g_kh + ((size_t)(b * Hc + h) * Sc) * Dc;
    const __half* vb = g_vh + ((size_t)(b * Hc + h) * Sc) * Dc;

    const int ntiles = (min(q0 + BM, len) + BN - 1) / BN;

    auto load_tile = [&](int it) {
        int k0 = it * BN, buf = it & 1;
#pragma unroll
        for (int i = tid * 8; i < BN * Dc; i += 128 * 8) {
            int r = i >> 6, d = i & 63;
            int gr = k0 + r;
            int nbytes = (gr < len) ? 16 : 0;
            uint32_t sk = (uint32_t)__cvta_generic_to_shared(&Ks[buf][r * STH + d]);
            uint32_t sv = (uint32_t)__cvta_generic_to_shared(&Vs[buf][r * STH + d]);
            cp16(sk, kb + (size_t)gr * Dc + d, nbytes);
            cp16(sv, vb + (size_t)gr * Dc + d, nbytes);
        }
        asm volatile("cp.async.commit_group;");
    };

    load_tile(0);

#pragma unroll
    for (int i = tid * 8; i < BM * Dc; i += 128 * 8) {
        int r = i >> 6, d = i & 63;
        uint4 val = (q0 + r < len) ? *(const uint4*)(qb + (size_t)(q0 + r) * Dc + d)
                                   : make_uint4(0u, 0u, 0u, 0u);
        *(uint4*)(Qs + r * STH + d) = val;
    }
    __syncthreads();

    uint32_t aq[4][4];
    {
        const __half* qp = Qs + (16 * w + (lane & 15)) * STH + ((lane >> 4) << 3);
#pragma unroll
        for (int kbk = 0; kbk < 4; kbk++)
            ldsm4(aq[kbk], qp + kbk * 16);
    }

    float o[8][4];
#pragma unroll
    for (int i = 0; i < 8; i++)
#pragma unroll
        for (int j = 0; j < 4; j++) o[i][j] = 0.f;
    float l0 = 0.f, l1 = 0.f;

    const int row0g = q0 + 16 * w + (lane >> 2);
    const int row1g = row0g + 8;
    // highest key column this warp ever needs (causal + keymask)
    const int kmax = min(q0 + 16 * w + 15, len - 1);

    for (int it = 0; it < ntiles; it++) {
        int k0 = it * BN, buf = it & 1;
        asm volatile("cp.async.wait_group 0;");
        __syncthreads();
        if (it + 1 < ntiles) load_tile(it + 1);

        // per-warp live-block bounds (warp-uniform)
        int rel = kmax - k0;                       // may be negative: all masked
        int nb_cnt  = min(8, max(0, (rel >> 3) + 1));
        int kbk_cnt = (nb_cnt + 1) >> 1;

        float s[8][4];
        {
            const __half* kp = Ks[buf] + (lane & 7) * STH + ((lane >> 3) << 3);
#pragma unroll
            for (int nb = 0; nb < 8; nb++) {
                if (nb < nb_cnt) {
#pragma unroll
                    for (int j = 0; j < 4; j++) s[nb][j] = 0.f;
                    const __half* kpn = kp + nb * 8 * STH;
                    uint32_t bkA[4], bkB[4];
                    ldsm4(bkA, kpn);
                    ldsm4(bkB, kpn + 32);
                    mma16(s[nb], aq[0], bkA[0], bkA[1]);
                    mma16(s[nb], aq[1], bkA[2], bkA[3]);
                    mma16(s[nb], aq[2], bkB[0], bkB[1]);
                    mma16(s[nb], aq[3], bkB[2], bkB[3]);
                }
            }
        }

        // mask (only on boundary tiles; bounded by nb_cnt)
        if (k0 + BN > kmax) {
#pragma unroll
            for (int nb = 0; nb < 8; nb++) {
                if (nb < nb_cnt) {
                    int cp = k0 + nb * 8 + 2 * (lane & 3);
                    if (cp     > row0g || cp     >= len) s[nb][0] = -1e30f;
                    if (cp + 1 > row0g || cp + 1 >= len) s[nb][1] = -1e30f;
                    if (cp     > row1g || cp     >= len) s[nb][2] = -1e30f;
                    if (cp + 1 > row1g || cp + 1 >= len) s[nb][3] = -1e30f;
                }
            }
        }

        // p = 2^s (scale folded into Q); accumulate l; pack P A-fragments.
        uint32_t ap[4][4];
#pragma unroll
        for (int kbk = 0; kbk < 4; kbk++) {
            if (kbk < kbk_cnt) {
                int n0 = 2 * kbk, n1 = 2 * kbk + 1;
                float p00 = ex2(s[n0][0]), p01 = ex2(s[n0][1]);
                float p02 = ex2(s[n0][2]), p03 = ex2(s[n0][3]);
                float p10 = 0.f, p11 = 0.f, p12 = 0.f, p13 = 0.f;
                if (n1 < nb_cnt) {
                    p10 = ex2(s[n1][0]); p11 = ex2(s[n1][1]);
                    p12 = ex2(s[n1][2]); p13 = ex2(s[n1][3]);
                }
                l0 += (p00 + p01) + (p10 + p11);
                l1 += (p02 + p03) + (p12 + p13);
                ap[kbk][0] = pack_h2(p00, p01);
                ap[kbk][1] = pack_h2(p02, p03);
                ap[kbk][2] = pack_h2(p10, p11);
                ap[kbk][3] = pack_h2(p12, p13);
            }
        }

        // O += P V (skip all-zero P k-blocks)
        {
            const __half* vp = Vs[buf] + (lane & 15) * STH + ((lane >> 4) << 3);
#pragma unroll
            for (int kbk = 0; kbk < 4; kbk++) {
                if (kbk < kbk_cnt) {
                    const __half* vpk = vp + kbk * 16 * STH;
#pragma unroll
                    for (int dp = 0; dp < 4; dp++) {
                        uint32_t bv[4];
                        ldsm4t(bv, vpk + dp * 16);
                        mma16(o[2 * dp],     ap[kbk], bv[0], bv[1]);
                        mma16(o[2 * dp + 1], ap[kbk], bv[2], bv[3]);
                    }
                }
            }
        }
    }

    // epilogue: single l-reduction across the quad, then scale + store
    {
#pragma unroll
        for (int off = 1; off < 4; off <<= 1) {
            l0 += __shfl_xor_sync(0xffffffffu, l0, off);
            l1 += __shfl_xor_sync(0xffffffffu, l1, off);
        }
        float inv0 = 1.f / l0, inv1 = 1.f / l1;
        size_t base = ((size_t)(b * Hc + h) * Sc) * Dc;
        int colb = 2 * (lane & 3);
#pragma unroll
        for (int db = 0; db < 8; db++) {
            if (row0g < len) {
                float2 t = make_float2(o[db][0] * inv0, o[db][1] * inv0);
                *(float2*)(out + base + (size_t)row0g * Dc + db * 8 + colb) = t;
            }
            if (row1g < len) {
                float2 t = make_float2(o[db][2] * inv1, o[db][3] * inv1);
                *(float2*)(out + base + (size_t)row1g * Dc + db * 8 + colb) = t;
            }
        }
    }
}

// ---------------------------------------------------------------------------
// Kernel 3: padded rows (pos >= len) = mean of V over rows [0, len).
// ---------------------------------------------------------------------------
__global__ void tail_kernel(const int* __restrict__ lens, float* __restrict__ out)
{
    int h = blockIdx.x, b = blockIdx.y;
    int len = lens[b];
    __shared__ float vsum[4][Dc];
    int tid = threadIdx.x;
    int d = tid & 63, g = tid >> 6;

    const __half* vb = g_vh + ((size_t)(b * Hc + h) * Sc) * Dc;
    float s = 0.f;
    for (int r = g; r < len; r += 4) s += __half2float(vb[(size_t)r * Dc + d]);
    vsum[g][d] = s;
    __syncthreads();
    if (g == 0) {
        float tot = vsum[0][d] + vsum[1][d] + vsum[2][d] + vsum[3][d];
        vsum[0][d] = tot / (float)max(len, 1);
    }
    __syncthreads();
    float mean = vsum[0][d];
    for (int r = len + g; r < Sc; r += 4)
        out[((size_t)(b * Hc + h) * Sc + r) * Dc + d] = mean;
}

// ---------------------------------------------------------------------------
extern "C" void kernel_launch(void* const* d_in, const int* in_sizes, int n_in,
                              void* d_out, int out_size)
{
    const float* q    = (const float*)d_in[0];
    const float* k    = (const float*)d_in[1];
    const float* v    = (const float*)d_in[2];
    const int*   lens = (const int*)d_in[5];
    float* out = (float*)d_out;

    (void)in_sizes; (void)n_in; (void)out_size;

    int prep_threads = Tc * 4 * 16;
    prep_kernel<<<(prep_threads + 127) / 128, 128>>>(q, k, v, lens);

    dim3 agrid(Sc / BM, Hc, Bc);
    attn_kernel<<<agrid, 128>>>(lens, out);

    dim3 tgrid(Hc, Bc);
    tail_kernel<<<tgrid, 256>>>(lens, out);
}

// round 7
// speedup vs baseline: 1.1479x; 1.1479x over previous
#include <cuda_runtime.h>
#include <cuda_fp16.h>
#include <math.h>
#include <stdint.h>

#define Bc 4
#define Sc 1024
#define Hc 16
#define Dc 64
#define Tc 2048
#define BM 64
#define BN 64
#define STH 72   // smem row stride in halves: 144B rows, 16B-aligned, ldmatrix conflict-free

// Q pre-scale: ATT_SCALE * log2(e), so softmax uses raw ex2.approx.
#define QSCALE 0.18033688011112042f

// Scratch (static device globals: allowed; no allocation). fp16 halves traffic.
__device__ __half g_qh[Bc*Hc*Sc*Dc];
__device__ __half g_kh[Bc*Hc*Sc*Dc];
__device__ __half g_vh[Bc*Hc*Sc*Dc];

__device__ __forceinline__ void ldsm4(uint32_t (&r)[4], const __half* p) {
    uint32_t a = (uint32_t)__cvta_generic_to_shared(p);
    asm volatile("ldmatrix.sync.aligned.m8n8.x4.shared.b16 {%0,%1,%2,%3}, [%4];"
                 : "=r"(r[0]), "=r"(r[1]), "=r"(r[2]), "=r"(r[3]) : "r"(a));
}
__device__ __forceinline__ void ldsm4t(uint32_t (&r)[4], const __half* p) {
    uint32_t a = (uint32_t)__cvta_generic_to_shared(p);
    asm volatile("ldmatrix.sync.aligned.m8n8.x4.trans.shared.b16 {%0,%1,%2,%3}, [%4];"
                 : "=r"(r[0]), "=r"(r[1]), "=r"(r[2]), "=r"(r[3]) : "r"(a));
}
__device__ __forceinline__ void mma16(float (&d)[4], const uint32_t (&a)[4],
                                      uint32_t b0, uint32_t b1) {
    asm volatile("mma.sync.aligned.m16n8k16.row.col.f32.f16.f16.f32 "
                 "{%0,%1,%2,%3},{%4,%5,%6,%7},{%8,%9},{%0,%1,%2,%3};"
                 : "+f"(d[0]), "+f"(d[1]), "+f"(d[2]), "+f"(d[3])
                 : "r"(a[0]), "r"(a[1]), "r"(a[2]), "r"(a[3]), "r"(b0), "r"(b1));
}
__device__ __forceinline__ uint32_t pack_h2(float x, float y) {
    __half2 h = __floats2half2_rn(x, y);
    return *reinterpret_cast<uint32_t*>(&h);
}
__device__ __forceinline__ float ex2(float x) {
    float r;
    asm("ex2.approx.f32 %0, %1;" : "=f"(r) : "f"(x));
    return r;
}
__device__ __forceinline__ void cp16(uint32_t saddr, const void* g, int src_bytes) {
    asm volatile("cp.async.cg.shared.global [%0], [%1], 16, %2;"
                 :: "r"(saddr), "l"(g), "r"(src_bytes));
}

// ---------------------------------------------------------------------------
// Kernel 1: ragged->padded scatter + RoPE, fp16 outputs, Q pre-scaled by
// 0.125*log2(e). One thread per (t, head-quad, even d2)  [R4 layout].
// ---------------------------------------------------------------------------
__global__ void prep_kernel(const float* __restrict__ q,
                            const float* __restrict__ k,
                            const float* __restrict__ v,
                            const int*   __restrict__ lens)
{
    int idx = blockIdx.x * blockDim.x + threadIdx.x;
    if (idx >= Tc * 4 * 16) return;
    int d2 = (idx & 15) * 2;       // even d2 in [0,32)
    int hq = (idx >> 4) & 3;       // head quad
    int t  = idx >> 6;

    int off = 0, b = 0, pos = 0;
#pragma unroll
    for (int i = 0; i < Bc; i++) {
        int L = __ldg(&lens[i]);
        if (t >= off) { b = i; pos = t - off; }
        off += L;
    }

    const float LOG2_10000_DIV32 = 0.4152410118609203f;
    float s0, c0, s1, c1;
    sincosf((float)pos * exp2f(-(float)d2 * LOG2_10000_DIV32), &s0, &c0);
    sincosf((float)pos * exp2f(-(float)(d2 + 1) * LOG2_10000_DIV32), &s1, &c1);

#pragma unroll
    for (int hh = 0; hh < 4; hh++) {
        int h = hq * 4 + hh;
        int src = (t * Hc + h) * Dc;
        float2 q1 = *(const float2*)(q + src + d2);
        float2 q2 = *(const float2*)(q + src + d2 + 32);
        float2 k1 = *(const float2*)(k + src + d2);
        float2 k2 = *(const float2*)(k + src + d2 + 32);
        float2 v1 = *(const float2*)(v + src + d2);
        float2 v2 = *(const float2*)(v + src + d2 + 32);

        int dst = ((b * Hc + h) * Sc + pos) * Dc;
        *(__half2*)(g_qh + dst + d2) =
            __floats2half2_rn((q1.x * c0 - q2.x * s0) * QSCALE,
                              (q1.y * c1 - q2.y * s1) * QSCALE);
        *(__half2*)(g_qh + dst + d2 + 32) =
            __floats2half2_rn((q2.x * c0 + q1.x * s0) * QSCALE,
                              (q2.y * c1 + q1.y * s1) * QSCALE);
        *(__half2*)(g_kh + dst + d2) =
            __floats2half2_rn(k1.x * c0 - k2.x * s0, k1.y * c1 - k2.y * s1);
        *(__half2*)(g_kh + dst + d2 + 32) =
            __floats2half2_rn(k2.x * c0 + k1.x * s0, k2.y * c1 + k1.y * s1);
        *(__half2*)(g_vh + dst + d2)      = __floats2half2_rn(v1.x, v1.y);
        *(__half2*)(g_vh + dst + d2 + 32) = __floats2half2_rn(v2.x, v2.y);
    }
}

// ---------------------------------------------------------------------------
// Kernel 2: causal flash attention, fp16 MMA, ex2-domain softmax (no max),
// 2-stage cp.async pipeline on K/V, deferred l-reduction.  [R4 structure]
// ---------------------------------------------------------------------------
__global__ void __launch_bounds__(128)
attn_kernel(const int* __restrict__ lens, float* __restrict__ out)
{
    int qt = blockIdx.x, h = blockIdx.y, b = blockIdx.z;
    int len = lens[b];
    int q0 = qt * BM;
    if (q0 >= len) return;

    __shared__ __half Qs[BM * STH];
    __shared__ __half Ks[2][BN * STH];
    __shared__ __half Vs[2][BN * STH];

    const int tid  = threadIdx.x;
    const int lane = tid & 31;
    const int w    = tid >> 5;

    const __half* qb = g_qh + ((size_t)(b * Hc + h) * Sc) * Dc;
    const __half* kb = g_kh + ((size_t)(b * Hc + h) * Sc) * Dc;
    const __half* vb = g_vh + ((size_t)(b * Hc + h) * Sc) * Dc;

    const int ntiles = (min(q0 + BM, len) + BN - 1) / BN;

    auto load_tile = [&](int it) {
        int k0 = it * BN, buf = it & 1;
#pragma unroll
        for (int i = tid * 8; i < BN * Dc; i += 128 * 8) {
            int r = i >> 6, d = i & 63;
            int gr = k0 + r;
            int nbytes = (gr < len) ? 16 : 0;
            uint32_t sk = (uint32_t)__cvta_generic_to_shared(&Ks[buf][r * STH + d]);
            uint32_t sv = (uint32_t)__cvta_generic_to_shared(&Vs[buf][r * STH + d]);
            cp16(sk, kb + (size_t)gr * Dc + d, nbytes);
            cp16(sv, vb + (size_t)gr * Dc + d, nbytes);
        }
        asm volatile("cp.async.commit_group;");
    };

    load_tile(0);

#pragma unroll
    for (int i = tid * 8; i < BM * Dc; i += 128 * 8) {
        int r = i >> 6, d = i & 63;
        uint4 val = (q0 + r < len) ? *(const uint4*)(qb + (size_t)(q0 + r) * Dc + d)
                                   : make_uint4(0u, 0u, 0u, 0u);
        *(uint4*)(Qs + r * STH + d) = val;
    }
    __syncthreads();

    uint32_t aq[4][4];
    {
        const __half* qp = Qs + (16 * w + (lane & 15)) * STH + ((lane >> 4) << 3);
#pragma unroll
        for (int kbk = 0; kbk < 4; kbk++)
            ldsm4(aq[kbk], qp + kbk * 16);
    }

    float o[8][4];
#pragma unroll
    for (int i = 0; i < 8; i++)
#pragma unroll
        for (int j = 0; j < 4; j++) o[i][j] = 0.f;
    float l0 = 0.f, l1 = 0.f;

    const int row0g = q0 + 16 * w + (lane >> 2);
    const int row1g = row0g + 8;

    for (int it = 0; it < ntiles; it++) {
        int k0 = it * BN, buf = it & 1;
        asm volatile("cp.async.wait_group 0;");
        __syncthreads();
        if (it + 1 < ntiles) load_tile(it + 1);

        // S = Q K^T  (scale and log2(e) folded into Q)
        float s[8][4];
        {
            const __half* kp = Ks[buf] + (lane & 7) * STH + ((lane >> 3) << 3);
#pragma unroll
            for (int nb = 0; nb < 8; nb++) {
#pragma unroll
                for (int j = 0; j < 4; j++) s[nb][j] = 0.f;
                const __half* kpn = kp + nb * 8 * STH;
                uint32_t bkA[4], bkB[4];
                ldsm4(bkA, kpn);
                ldsm4(bkB, kpn + 32);
                mma16(s[nb], aq[0], bkA[0], bkA[1]);
                mma16(s[nb], aq[1], bkA[2], bkA[3]);
                mma16(s[nb], aq[2], bkB[0], bkB[1]);
                mma16(s[nb], aq[3], bkB[2], bkB[3]);
            }
        }

        // mask only on diagonal/len-crossing tiles (warp-uniform branch)
        if (k0 + BN > q0 + 16 * w || k0 + BN > len) {
#pragma unroll
            for (int nb = 0; nb < 8; nb++) {
                int cp = k0 + nb * 8 + 2 * (lane & 3);
                if (cp     > row0g || cp     >= len) s[nb][0] = -1e30f;
                if (cp + 1 > row0g || cp + 1 >= len) s[nb][1] = -1e30f;
                if (cp     > row1g || cp     >= len) s[nb][2] = -1e30f;
                if (cp + 1 > row1g || cp + 1 >= len) s[nb][3] = -1e30f;
            }
        }

        // p = 2^s (no max subtraction: exponent bounded); accumulate l;
        // pack directly into P A-fragments.
        uint32_t ap[4][4];
#pragma unroll
        for (int kbk = 0; kbk < 4; kbk++) {
            int n0 = 2 * kbk, n1 = 2 * kbk + 1;
            float p00 = ex2(s[n0][0]), p01 = ex2(s[n0][1]);
            float p02 = ex2(s[n0][2]), p03 = ex2(s[n0][3]);
            float p10 = ex2(s[n1][0]), p11 = ex2(s[n1][1]);
            float p12 = ex2(s[n1][2]), p13 = ex2(s[n1][3]);
            l0 += (p00 + p01) + (p10 + p11);
            l1 += (p02 + p03) + (p12 + p13);
            ap[kbk][0] = pack_h2(p00, p01);
            ap[kbk][1] = pack_h2(p02, p03);
            ap[kbk][2] = pack_h2(p10, p11);
            ap[kbk][3] = pack_h2(p12, p13);
        }

        // O += P V
        {
            const __half* vp = Vs[buf] + (lane & 15) * STH + ((lane >> 4) << 3);
#pragma unroll
            for (int kbk = 0; kbk < 4; kbk++) {
                const __half* vpk = vp + kbk * 16 * STH;
#pragma unroll
                for (int dp = 0; dp < 4; dp++) {
                    uint32_t bv[4];
                    ldsm4t(bv, vpk + dp * 16);
                    mma16(o[2 * dp],     ap[kbk], bv[0], bv[1]);
                    mma16(o[2 * dp + 1], ap[kbk], bv[2], bv[3]);
                }
            }
        }
    }

    // epilogue: reduce l across the quad once, then scale + store
    {
#pragma unroll
        for (int off = 1; off < 4; off <<= 1) {
            l0 += __shfl_xor_sync(0xffffffffu, l0, off);
            l1 += __shfl_xor_sync(0xffffffffu, l1, off);
        }
        float inv0 = 1.f / l0, inv1 = 1.f / l1;
        size_t base = ((size_t)(b * Hc + h) * Sc) * Dc;
        int colb = 2 * (lane & 3);
#pragma unroll
        for (int db = 0; db < 8; db++) {
            if (row0g < len) {
                float2 t = make_float2(o[db][0] * inv0, o[db][1] * inv0);
                *(float2*)(out + base + (size_t)row0g * Dc + db * 8 + colb) = t;
            }
            if (row1g < len) {
                float2 t = make_float2(o[db][2] * inv1, o[db][3] * inv1);
                *(float2*)(out + base + (size_t)row1g * Dc + db * 8 + colb) = t;
            }
        }
    }
}

// ---------------------------------------------------------------------------
// Kernel 3: padded rows (pos >= len) = mean of V over rows [0, len).
// ---------------------------------------------------------------------------
__global__ void tail_kernel(const int* __restrict__ lens, float* __restrict__ out)
{
    int h = blockIdx.x, b = blockIdx.y;
    int len = lens[b];
    __shared__ float vsum[4][Dc];
    int tid = threadIdx.x;
    int d = tid & 63, g = tid >> 6;

    const __half* vb = g_vh + ((size_t)(b * Hc + h) * Sc) * Dc;
    float s = 0.f;
    for (int r = g; r < len; r += 4) s += __half2float(vb[(size_t)r * Dc + d]);
    vsum[g][d] = s;
    __syncthreads();
    if (g == 0) {
        float tot = vsum[0][d] + vsum[1][d] + vsum[2][d] + vsum[3][d];
        vsum[0][d] = tot / (float)max(len, 1);
    }
    __syncthreads();
    float mean = vsum[0][d];
    for (int r = len + g; r < Sc; r += 4)
        out[((size_t)(b * Hc + h) * Sc + r) * Dc + d] = mean;
}

// ---------------------------------------------------------------------------
extern "C" void kernel_launch(void* const* d_in, const int* in_sizes, int n_in,
                              void* d_out, int out_size)
{
    const float* q    = (const float*)d_in[0];
    const float* k    = (const float*)d_in[1];
    const float* v    = (const float*)d_in[2];
    const int*   lens = (const int*)d_in[5];
    float* out = (float*)d_out;

    (void)in_sizes; (void)n_in; (void)out_size;

    int prep_threads = Tc * 4 * 16;
    prep_kernel<<<(prep_threads + 255) / 256, 256>>>(q, k, v, lens);

    dim3 agrid(Sc / BM, Hc, Bc);
    attn_kernel<<<agrid, 128>>>(lens, out);

    dim3 tgrid(Hc, Bc);
    tail_kernel<<<tgrid, 256>>>(lens, out);
}

// round 8
// speedup vs baseline: 1.1590x; 1.0096x over previous
#include <cuda_runtime.h>
#include <cuda_fp16.h>
#include <math.h>
#include <stdint.h>

#define Bc 4
#define Sc 1024
#define Hc 16
#define Dc 64
#define Tc 2048
#define BM 64
#define BN 64
#define STH 72   // smem row stride in halves: 144B rows, 16B-aligned, ldmatrix conflict-free

// Q pre-scale: ATT_SCALE * log2(e), so softmax uses raw ex2.approx.
#define QSCALE 0.18033688011112042f

// Scratch (static device globals: allowed; no allocation). fp16 halves traffic.
__device__ __half g_qh[Bc*Hc*Sc*Dc];
__device__ __half g_kh[Bc*Hc*Sc*Dc];
__device__ __half g_vh[Bc*Hc*Sc*Dc];

__device__ __forceinline__ void ldsm4(uint32_t (&r)[4], const __half* p) {
    uint32_t a = (uint32_t)__cvta_generic_to_shared(p);
    asm volatile("ldmatrix.sync.aligned.m8n8.x4.shared.b16 {%0,%1,%2,%3}, [%4];"
                 : "=r"(r[0]), "=r"(r[1]), "=r"(r[2]), "=r"(r[3]) : "r"(a));
}
__device__ __forceinline__ void ldsm4t(uint32_t (&r)[4], const __half* p) {
    uint32_t a = (uint32_t)__cvta_generic_to_shared(p);
    asm volatile("ldmatrix.sync.aligned.m8n8.x4.trans.shared.b16 {%0,%1,%2,%3}, [%4];"
                 : "=r"(r[0]), "=r"(r[1]), "=r"(r[2]), "=r"(r[3]) : "r"(a));
}
__device__ __forceinline__ void mma16(float (&d)[4], const uint32_t (&a)[4],
                                      uint32_t b0, uint32_t b1) {
    asm volatile("mma.sync.aligned.m16n8k16.row.col.f32.f16.f16.f32 "
                 "{%0,%1,%2,%3},{%4,%5,%6,%7},{%8,%9},{%0,%1,%2,%3};"
                 : "+f"(d[0]), "+f"(d[1]), "+f"(d[2]), "+f"(d[3])
                 : "r"(a[0]), "r"(a[1]), "r"(a[2]), "r"(a[3]), "r"(b0), "r"(b1));
}
__device__ __forceinline__ uint32_t pack_h2(float x, float y) {
    __half2 h = __floats2half2_rn(x, y);
    return *reinterpret_cast<uint32_t*>(&h);
}
__device__ __forceinline__ float ex2(float x) {
    float r;
    asm("ex2.approx.f32 %0, %1;" : "=f"(r) : "f"(x));
    return r;
}
__device__ __forceinline__ void cp16(uint32_t saddr, const void* g, int src_bytes) {
    asm volatile("cp.async.cg.shared.global [%0], [%1], 16, %2;"
                 :: "r"(saddr), "l"(g), "r"(src_bytes));
}

// ---------------------------------------------------------------------------
// Kernel 1: ragged->padded scatter + RoPE, fp16 outputs, Q pre-scaled by
// 0.125*log2(e). One thread per (t, head-PAIR, even d2): 2x the threads of
// the head-quad layout for latency hiding (occupancy was 39.7%).
// ---------------------------------------------------------------------------
__global__ void prep_kernel(const float* __restrict__ q,
                            const float* __restrict__ k,
                            const float* __restrict__ v,
                            const int*   __restrict__ lens)
{
    int idx = blockIdx.x * blockDim.x + threadIdx.x;
    if (idx >= Tc * 8 * 16) return;
    int d2 = (idx & 15) * 2;       // even d2 in [0,32)
    int hp = (idx >> 4) & 7;       // head pair: heads 2*hp, 2*hp+1
    int t  = idx >> 7;

    int off = 0, b = 0, pos = 0;
#pragma unroll
    for (int i = 0; i < Bc; i++) {
        int L = __ldg(&lens[i]);
        if (t >= off) { b = i; pos = t - off; }
        off += L;
    }

    const float LOG2_10000_DIV32 = 0.4152410118609203f;
    float s0, c0, s1, c1;
    sincosf((float)pos * exp2f(-(float)d2 * LOG2_10000_DIV32), &s0, &c0);
    sincosf((float)pos * exp2f(-(float)(d2 + 1) * LOG2_10000_DIV32), &s1, &c1);

#pragma unroll
    for (int hh = 0; hh < 2; hh++) {
        int h = hp * 2 + hh;
        int src = (t * Hc + h) * Dc;
        float2 q1 = *(const float2*)(q + src + d2);
        float2 q2 = *(const float2*)(q + src + d2 + 32);
        float2 k1 = *(const float2*)(k + src + d2);
        float2 k2 = *(const float2*)(k + src + d2 + 32);
        float2 v1 = *(const float2*)(v + src + d2);
        float2 v2 = *(const float2*)(v + src + d2 + 32);

        int dst = ((b * Hc + h) * Sc + pos) * Dc;
        *(__half2*)(g_qh + dst + d2) =
            __floats2half2_rn((q1.x * c0 - q2.x * s0) * QSCALE,
                              (q1.y * c1 - q2.y * s1) * QSCALE);
        *(__half2*)(g_qh + dst + d2 + 32) =
            __floats2half2_rn((q2.x * c0 + q1.x * s0) * QSCALE,
                              (q2.y * c1 + q1.y * s1) * QSCALE);
        *(__half2*)(g_kh + dst + d2) =
            __floats2half2_rn(k1.x * c0 - k2.x * s0, k1.y * c1 - k2.y * s1);
        *(__half2*)(g_kh + dst + d2 + 32) =
            __floats2half2_rn(k2.x * c0 + k1.x * s0, k2.y * c1 + k1.y * s1);
        *(__half2*)(g_vh + dst + d2)      = __floats2half2_rn(v1.x, v1.y);
        *(__half2*)(g_vh + dst + d2 + 32) = __floats2half2_rn(v2.x, v2.y);
    }
}

// ---------------------------------------------------------------------------
// Kernel 2: causal flash attention, fp16 MMA, ex2-domain softmax (no max),
// 2-stage cp.async pipeline on K/V, deferred l-reduction. Heavy CTAs first.
// ---------------------------------------------------------------------------
__global__ void __launch_bounds__(128)
attn_kernel(const int* __restrict__ lens, float* __restrict__ out)
{
    int qt = (Sc / BM - 1) - blockIdx.x;   // heavy-first: longest k-loops launch first
    int h = blockIdx.y, b = blockIdx.z;
    int len = lens[b];
    int q0 = qt * BM;
    if (q0 >= len) return;

    __shared__ __half Qs[BM * STH];
    __shared__ __half Ks[2][BN * STH];
    __shared__ __half Vs[2][BN * STH];

    const int tid  = threadIdx.x;
    const int lane = tid & 31;
    const int w    = tid >> 5;

    const __half* qb = g_qh + ((size_t)(b * Hc + h) * Sc) * Dc;
    const __half* kb = g_kh + ((size_t)(b * Hc + h) * Sc) * Dc;
    const __half* vb = g_vh + ((size_t)(b * Hc + h) * Sc) * Dc;

    const int ntiles = (min(q0 + BM, len) + BN - 1) / BN;

    auto load_tile = [&](int it) {
        int k0 = it * BN, buf = it & 1;
#pragma unroll
        for (int i = tid * 8; i < BN * Dc; i += 128 * 8) {
            int r = i >> 6, d = i & 63;
            int gr = k0 + r;
            int nbytes = (gr < len) ? 16 : 0;
            uint32_t sk = (uint32_t)__cvta_generic_to_shared(&Ks[buf][r * STH + d]);
            uint32_t sv = (uint32_t)__cvta_generic_to_shared(&Vs[buf][r * STH + d]);
            cp16(sk, kb + (size_t)gr * Dc + d, nbytes);
            cp16(sv, vb + (size_t)gr * Dc + d, nbytes);
        }
        asm volatile("cp.async.commit_group;");
    };

    load_tile(0);

#pragma unroll
    for (int i = tid * 8; i < BM * Dc; i += 128 * 8) {
        int r = i >> 6, d = i & 63;
        uint4 val = (q0 + r < len) ? *(const uint4*)(qb + (size_t)(q0 + r) * Dc + d)
                                   : make_uint4(0u, 0u, 0u, 0u);
        *(uint4*)(Qs + r * STH + d) = val;
    }
    __syncthreads();

    uint32_t aq[4][4];
    {
        const __half* qp = Qs + (16 * w + (lane & 15)) * STH + ((lane >> 4) << 3);
#pragma unroll
        for (int kbk = 0; kbk < 4; kbk++)
            ldsm4(aq[kbk], qp + kbk * 16);
    }

    float o[8][4];
#pragma unroll
    for (int i = 0; i < 8; i++)
#pragma unroll
        for (int j = 0; j < 4; j++) o[i][j] = 0.f;
    float l0 = 0.f, l1 = 0.f;

    const int row0g = q0 + 16 * w + (lane >> 2);
    const int row1g = row0g + 8;

    for (int it = 0; it < ntiles; it++) {
        int k0 = it * BN, buf = it & 1;
        asm volatile("cp.async.wait_group 0;");
        __syncthreads();
        if (it + 1 < ntiles) load_tile(it + 1);

        // S = Q K^T  (scale and log2(e) folded into Q)
        float s[8][4];
        {
            const __half* kp = Ks[buf] + (lane & 7) * STH + ((lane >> 3) << 3);
#pragma unroll
            for (int nb = 0; nb < 8; nb++) {
#pragma unroll
                for (int j = 0; j < 4; j++) s[nb][j] = 0.f;
                const __half* kpn = kp + nb * 8 * STH;
                uint32_t bkA[4], bkB[4];
                ldsm4(bkA, kpn);
                ldsm4(bkB, kpn + 32);
                mma16(s[nb], aq[0], bkA[0], bkA[1]);
                mma16(s[nb], aq[1], bkA[2], bkA[3]);
                mma16(s[nb], aq[2], bkB[0], bkB[1]);
                mma16(s[nb], aq[3], bkB[2], bkB[3]);
            }
        }

        // mask only on diagonal/len-crossing tiles (warp-uniform branch)
        if (k0 + BN > q0 + 16 * w || k0 + BN > len) {
#pragma unroll
            for (int nb = 0; nb < 8; nb++) {
                int cp = k0 + nb * 8 + 2 * (lane & 3);
                if (cp     > row0g || cp     >= len) s[nb][0] = -1e30f;
                if (cp + 1 > row0g || cp + 1 >= len) s[nb][1] = -1e30f;
                if (cp     > row1g || cp     >= len) s[nb][2] = -1e30f;
                if (cp + 1 > row1g || cp + 1 >= len) s[nb][3] = -1e30f;
            }
        }

        // p = 2^s; accumulate l; pack directly into P A-fragments.
        uint32_t ap[4][4];
#pragma unroll
        for (int kbk = 0; kbk < 4; kbk++) {
            int n0 = 2 * kbk, n1 = 2 * kbk + 1;
            float p00 = ex2(s[n0][0]), p01 = ex2(s[n0][1]);
            float p02 = ex2(s[n0][2]), p03 = ex2(s[n0][3]);
            float p10 = ex2(s[n1][0]), p11 = ex2(s[n1][1]);
            float p12 = ex2(s[n1][2]), p13 = ex2(s[n1][3]);
            l0 += (p00 + p01) + (p10 + p11);
            l1 += (p02 + p03) + (p12 + p13);
            ap[kbk][0] = pack_h2(p00, p01);
            ap[kbk][1] = pack_h2(p02, p03);
            ap[kbk][2] = pack_h2(p10, p11);
            ap[kbk][3] = pack_h2(p12, p13);
        }

        // O += P V
        {
            const __half* vp = Vs[buf] + (lane & 15) * STH + ((lane >> 4) << 3);
#pragma unroll
            for (int kbk = 0; kbk < 4; kbk++) {
                const __half* vpk = vp + kbk * 16 * STH;
#pragma unroll
                for (int dp = 0; dp < 4; dp++) {
                    uint32_t bv[4];
                    ldsm4t(bv, vpk + dp * 16);
                    mma16(o[2 * dp],     ap[kbk], bv[0], bv[1]);
                    mma16(o[2 * dp + 1], ap[kbk], bv[2], bv[3]);
                }
            }
        }
    }

    // epilogue: reduce l across the quad once, then scale + store
    {
#pragma unroll
        for (int off = 1; off < 4; off <<= 1) {
            l0 += __shfl_xor_sync(0xffffffffu, l0, off);
            l1 += __shfl_xor_sync(0xffffffffu, l1, off);
        }
        float inv0 = 1.f / l0, inv1 = 1.f / l1;
        size_t base = ((size_t)(b * Hc + h) * Sc) * Dc;
        int colb = 2 * (lane & 3);
#pragma unroll
        for (int db = 0; db < 8; db++) {
            if (row0g < len) {
                float2 t = make_float2(o[db][0] * inv0, o[db][1] * inv0);
                *(float2*)(out + base + (size_t)row0g * Dc + db * 8 + colb) = t;
            }
            if (row1g < len) {
                float2 t = make_float2(o[db][2] * inv1, o[db][3] * inv1);
                *(float2*)(out + base + (size_t)row1g * Dc + db * 8 + colb) = t;
            }
        }
    }
}

// ---------------------------------------------------------------------------
// Kernel 3: padded rows (pos >= len) = mean of V over rows [0, len).
// ---------------------------------------------------------------------------
__global__ void tail_kernel(const int* __restrict__ lens, float* __restrict__ out)
{
    int h = blockIdx.x, b = blockIdx.y;
    int len = lens[b];
    __shared__ float vsum[4][Dc];
    int tid = threadIdx.x;
    int d = tid & 63, g = tid >> 6;

    const __half* vb = g_vh + ((size_t)(b * Hc + h) * Sc) * Dc;
    float s = 0.f;
    for (int r = g; r < len; r += 4) s += __half2float(vb[(size_t)r * Dc + d]);
    vsum[g][d] = s;
    __syncthreads();
    if (g == 0) {
        float tot = vsum[0][d] + vsum[1][d] + vsum[2][d] + vsum[3][d];
        vsum[0][d] = tot / (float)max(len, 1);
    }
    __syncthreads();
    float mean = vsum[0][d];
    for (int r = len + g; r < Sc; r += 4)
        out[((size_t)(b * Hc + h) * Sc + r) * Dc + d] = mean;
}

// ---------------------------------------------------------------------------
extern "C" void kernel_launch(void* const* d_in, const int* in_sizes, int n_in,
                              void* d_out, int out_size)
{
    const float* q    = (const float*)d_in[0];
    const float* k    = (const float*)d_in[1];
    const float* v    = (const float*)d_in[2];
    const int*   lens = (const int*)d_in[5];
    float* out = (float*)d_out;

    (void)in_sizes; (void)n_in; (void)out_size;

    int prep_threads = Tc * 8 * 16;
    prep_kernel<<<(prep_threads + 255) / 256, 256>>>(q, k, v, lens);

    dim3 agrid(Sc / BM, Hc, Bc);
    attn_kernel<<<agrid, 128>>>(lens, out);

    dim3 tgrid(Hc, Bc);
    tail_kernel<<<tgrid, 256>>>(lens, out);
}

// round 9
// speedup vs baseline: 1.5094x; 1.3024x over previous
#include <cuda_runtime.h>
#include <cuda_fp16.h>
#include <math.h>
#include <stdint.h>

#define Bc 4
#define Sc 1024
#define Hc 16
#define Dc 64
#define Tc 2048
#define BM 64
#define BN 64
#define STH 72   // smem row stride in halves: 144B rows, 16B-aligned, ldmatrix conflict-free

// Q pre-scale: ATT_SCALE * log2(e), so softmax uses raw ex2.approx.
#define QSCALE 0.18033688011112042f

// Scratch (static device globals: allowed; no allocation). fp16 halves traffic.
__device__ __half g_qh[Bc*Hc*Sc*Dc];
__device__ __half g_kh[Bc*Hc*Sc*Dc];
__device__ __half g_vh[Bc*Hc*Sc*Dc];

__device__ __forceinline__ void ldsm4(uint32_t (&r)[4], const __half* p) {
    uint32_t a = (uint32_t)__cvta_generic_to_shared(p);
    asm volatile("ldmatrix.sync.aligned.m8n8.x4.shared.b16 {%0,%1,%2,%3}, [%4];"
                 : "=r"(r[0]), "=r"(r[1]), "=r"(r[2]), "=r"(r[3]) : "r"(a));
}
__device__ __forceinline__ void ldsm4t(uint32_t (&r)[4], const __half* p) {
    uint32_t a = (uint32_t)__cvta_generic_to_shared(p);
    asm volatile("ldmatrix.sync.aligned.m8n8.x4.trans.shared.b16 {%0,%1,%2,%3}, [%4];"
                 : "=r"(r[0]), "=r"(r[1]), "=r"(r[2]), "=r"(r[3]) : "r"(a));
}
__device__ __forceinline__ void mma16(float (&d)[4], const uint32_t (&a)[4],
                                      uint32_t b0, uint32_t b1) {
    asm volatile("mma.sync.aligned.m16n8k16.row.col.f32.f16.f16.f32 "
                 "{%0,%1,%2,%3},{%4,%5,%6,%7},{%8,%9},{%0,%1,%2,%3};"
                 : "+f"(d[0]), "+f"(d[1]), "+f"(d[2]), "+f"(d[3])
                 : "r"(a[0]), "r"(a[1]), "r"(a[2]), "r"(a[3]), "r"(b0), "r"(b1));
}
__device__ __forceinline__ uint32_t pack_h2(float x, float y) {
    __half2 h = __floats2half2_rn(x, y);
    return *reinterpret_cast<uint32_t*>(&h);
}
__device__ __forceinline__ float ex2(float x) {
    float r;
    asm("ex2.approx.f32 %0, %1;" : "=f"(r) : "f"(x));
    return r;
}
__device__ __forceinline__ void cp16(uint32_t saddr, const void* g, int src_bytes) {
    asm volatile("cp.async.cg.shared.global [%0], [%1], 16, %2;"
                 :: "r"(saddr), "l"(g), "r"(src_bytes));
}

// ---------------------------------------------------------------------------
// Kernel 1: ragged->padded scatter + RoPE, fp16 outputs, Q pre-scaled by
// 0.125*log2(e). One thread per (t, head-PAIR, even d2).
// ---------------------------------------------------------------------------
__global__ void prep_kernel(const float* __restrict__ q,
                            const float* __restrict__ k,
                            const float* __restrict__ v,
                            const int*   __restrict__ lens)
{
    int idx = blockIdx.x * blockDim.x + threadIdx.x;
    if (idx >= Tc * 8 * 16) return;
    int d2 = (idx & 15) * 2;       // even d2 in [0,32)
    int hp = (idx >> 4) & 7;       // head pair: heads 2*hp, 2*hp+1
    int t  = idx >> 7;

    int off = 0, b = 0, pos = 0;
#pragma unroll
    for (int i = 0; i < Bc; i++) {
        int L = __ldg(&lens[i]);
        if (t >= off) { b = i; pos = t - off; }
        off += L;
    }

    const float LOG2_10000_DIV32 = 0.4152410118609203f;
    float s0, c0, s1, c1;
    sincosf((float)pos * exp2f(-(float)d2 * LOG2_10000_DIV32), &s0, &c0);
    sincosf((float)pos * exp2f(-(float)(d2 + 1) * LOG2_10000_DIV32), &s1, &c1);

#pragma unroll
    for (int hh = 0; hh < 2; hh++) {
        int h = hp * 2 + hh;
        int src = (t * Hc + h) * Dc;
        float2 q1 = *(const float2*)(q + src + d2);
        float2 q2 = *(const float2*)(q + src + d2 + 32);
        float2 k1 = *(const float2*)(k + src + d2);
        float2 k2 = *(const float2*)(k + src + d2 + 32);
        float2 v1 = *(const float2*)(v + src + d2);
        float2 v2 = *(const float2*)(v + src + d2 + 32);

        int dst = ((b * Hc + h) * Sc + pos) * Dc;
        *(__half2*)(g_qh + dst + d2) =
            __floats2half2_rn((q1.x * c0 - q2.x * s0) * QSCALE,
                              (q1.y * c1 - q2.y * s1) * QSCALE);
        *(__half2*)(g_qh + dst + d2 + 32) =
            __floats2half2_rn((q2.x * c0 + q1.x * s0) * QSCALE,
                              (q2.y * c1 + q1.y * s1) * QSCALE);
        *(__half2*)(g_kh + dst + d2) =
            __floats2half2_rn(k1.x * c0 - k2.x * s0, k1.y * c1 - k2.y * s1);
        *(__half2*)(g_kh + dst + d2 + 32) =
            __floats2half2_rn(k2.x * c0 + k1.x * s0, k2.y * c1 + k1.y * s1);
        *(__half2*)(g_vh + dst + d2)      = __floats2half2_rn(v1.x, v1.y);
        *(__half2*)(g_vh + dst + d2 + 32) = __floats2half2_rn(v2.x, v2.y);
    }
}

// ---------------------------------------------------------------------------
// Kernel 2: causal flash attention, fp16 MMA, ex2-domain softmax (no max).
// Split K/V cp.async commit groups: V arrival overlapped by the S phase.
// First-inactive CTA per (h,b) does the padded-row V-mean fill (fused tail).
// ---------------------------------------------------------------------------
__global__ void __launch_bounds__(128)
attn_kernel(const int* __restrict__ lens, float* __restrict__ out)
{
    int qt = (Sc / BM - 1) - blockIdx.x;   // heavy-first
    int h = blockIdx.y, b = blockIdx.z;
    int len = lens[b];
    int q0 = qt * BM;

    const int tid  = threadIdx.x;

    if (q0 >= len) {
        // ---- fused tail: only the FIRST inactive qtile fills padded rows ----
        if (q0 - BM >= len) return;
        __shared__ float vsum[2][Dc];
        int d = tid & 63, g = tid >> 6;    // 2 row-groups of 64 threads
        const __half* vb = g_vh + ((size_t)(b * Hc + h) * Sc) * Dc;
        float s = 0.f;
        for (int r = g; r < len; r += 2) s += __half2float(vb[(size_t)r * Dc + d]);
        vsum[g][d] = s;
        __syncthreads();
        if (g == 0) vsum[0][d] = (vsum[0][d] + vsum[1][d]) / (float)max(len, 1);
        __syncthreads();
        float mean = vsum[0][d];
        for (int r = len + g; r < Sc; r += 2)
            out[((size_t)(b * Hc + h) * Sc + r) * Dc + d] = mean;
        return;
    }

    __shared__ __half Qs[BM * STH];
    __shared__ __half Ks[2][BN * STH];
    __shared__ __half Vs[2][BN * STH];

    const int lane = tid & 31;
    const int w    = tid >> 5;

    const __half* qb = g_qh + ((size_t)(b * Hc + h) * Sc) * Dc;
    const __half* kb = g_kh + ((size_t)(b * Hc + h) * Sc) * Dc;
    const __half* vb = g_vh + ((size_t)(b * Hc + h) * Sc) * Dc;

    const int ntiles = (min(q0 + BM, len) + BN - 1) / BN;

    // K and V in SEPARATE commit groups (K first, then V)
    auto load_tile = [&](int it) {
        int k0 = it * BN, buf = it & 1;
#pragma unroll
        for (int i = tid * 8; i < BN * Dc; i += 128 * 8) {
            int r = i >> 6, d = i & 63;
            int gr = k0 + r;
            int nbytes = (gr < len) ? 16 : 0;
            uint32_t sk = (uint32_t)__cvta_generic_to_shared(&Ks[buf][r * STH + d]);
            cp16(sk, kb + (size_t)gr * Dc + d, nbytes);
        }
        asm volatile("cp.async.commit_group;");
#pragma unroll
        for (int i = tid * 8; i < BN * Dc; i += 128 * 8) {
            int r = i >> 6, d = i & 63;
            int gr = k0 + r;
            int nbytes = (gr < len) ? 16 : 0;
            uint32_t sv = (uint32_t)__cvta_generic_to_shared(&Vs[buf][r * STH + d]);
            cp16(sv, vb + (size_t)gr * Dc + d, nbytes);
        }
        asm volatile("cp.async.commit_group;");
    };

    load_tile(0);

#pragma unroll
    for (int i = tid * 8; i < BM * Dc; i += 128 * 8) {
        int r = i >> 6, d = i & 63;
        uint4 val = (q0 + r < len) ? *(const uint4*)(qb + (size_t)(q0 + r) * Dc + d)
                                   : make_uint4(0u, 0u, 0u, 0u);
        *(uint4*)(Qs + r * STH + d) = val;
    }
    __syncthreads();

    uint32_t aq[4][4];
    {
        const __half* qp = Qs + (16 * w + (lane & 15)) * STH + ((lane >> 4) << 3);
#pragma unroll
        for (int kbk = 0; kbk < 4; kbk++)
            ldsm4(aq[kbk], qp + kbk * 16);
    }

    float o[8][4];
#pragma unroll
    for (int i = 0; i < 8; i++)
#pragma unroll
        for (int j = 0; j < 4; j++) o[i][j] = 0.f;
    float l0 = 0.f, l1 = 0.f;

    const int row0g = q0 + 16 * w + (lane >> 2);
    const int row1g = row0g + 8;

    for (int it = 0; it < ntiles; it++) {
        int k0 = it * BN, buf = it & 1;
        // K tile ready (V of this tile may still be in flight)
        asm volatile("cp.async.wait_group 1;");
        __syncthreads();
        bool more = (it + 1 < ntiles);
        if (more) load_tile(it + 1);

        // S = Q K^T  (scale and log2(e) folded into Q)
        float s[8][4];
        {
            const __half* kp = Ks[buf] + (lane & 7) * STH + ((lane >> 3) << 3);
#pragma unroll
            for (int nb = 0; nb < 8; nb++) {
#pragma unroll
                for (int j = 0; j < 4; j++) s[nb][j] = 0.f;
                const __half* kpn = kp + nb * 8 * STH;
                uint32_t bkA[4], bkB[4];
                ldsm4(bkA, kpn);
                ldsm4(bkB, kpn + 32);
                mma16(s[nb], aq[0], bkA[0], bkA[1]);
                mma16(s[nb], aq[1], bkA[2], bkA[3]);
                mma16(s[nb], aq[2], bkB[0], bkB[1]);
                mma16(s[nb], aq[3], bkB[2], bkB[3]);
            }
        }

        // mask only on diagonal/len-crossing tiles (warp-uniform branch)
        if (k0 + BN > q0 + 16 * w || k0 + BN > len) {
#pragma unroll
            for (int nb = 0; nb < 8; nb++) {
                int cp = k0 + nb * 8 + 2 * (lane & 3);
                if (cp     > row0g || cp     >= len) s[nb][0] = -1e30f;
                if (cp + 1 > row0g || cp + 1 >= len) s[nb][1] = -1e30f;
                if (cp     > row1g || cp     >= len) s[nb][2] = -1e30f;
                if (cp + 1 > row1g || cp + 1 >= len) s[nb][3] = -1e30f;
            }
        }

        // p = 2^s; accumulate l; pack directly into P A-fragments.
        uint32_t ap[4][4];
#pragma unroll
        for (int kbk = 0; kbk < 4; kbk++) {
            int n0 = 2 * kbk, n1 = 2 * kbk + 1;
            float p00 = ex2(s[n0][0]), p01 = ex2(s[n0][1]);
            float p02 = ex2(s[n0][2]), p03 = ex2(s[n0][3]);
            float p10 = ex2(s[n1][0]), p11 = ex2(s[n1][1]);
            float p12 = ex2(s[n1][2]), p13 = ex2(s[n1][3]);
            l0 += (p00 + p01) + (p10 + p11);
            l1 += (p02 + p03) + (p12 + p13);
            ap[kbk][0] = pack_h2(p00, p01);
            ap[kbk][1] = pack_h2(p02, p03);
            ap[kbk][2] = pack_h2(p10, p11);
            ap[kbk][3] = pack_h2(p12, p13);
        }

        // now V must be resident: if loads for it+1 are outstanding the two
        // newest groups are K_{it+1},V_{it+1} -> wait_group 2 drains V_it;
        // on the last iteration nothing newer exists -> wait_group 0.
        if (more) { asm volatile("cp.async.wait_group 2;"); }
        else      { asm volatile("cp.async.wait_group 0;"); }
        __syncthreads();

        // O += P V
        {
            const __half* vp = Vs[buf] + (lane & 15) * STH + ((lane >> 4) << 3);
#pragma unroll
            for (int kbk = 0; kbk < 4; kbk++) {
                const __half* vpk = vp + kbk * 16 * STH;
#pragma unroll
                for (int dp = 0; dp < 4; dp++) {
                    uint32_t bv[4];
                    ldsm4t(bv, vpk + dp * 16);
                    mma16(o[2 * dp],     ap[kbk], bv[0], bv[1]);
                    mma16(o[2 * dp + 1], ap[kbk], bv[2], bv[3]);
                }
            }
        }
    }

    // epilogue: reduce l across the quad once, then scale + store
    {
#pragma unroll
        for (int off = 1; off < 4; off <<= 1) {
            l0 += __shfl_xor_sync(0xffffffffu, l0, off);
            l1 += __shfl_xor_sync(0xffffffffu, l1, off);
        }
        float inv0 = 1.f / l0, inv1 = 1.f / l1;
        size_t base = ((size_t)(b * Hc + h) * Sc) * Dc;
        int colb = 2 * (lane & 3);
#pragma unroll
        for (int db = 0; db < 8; db++) {
            if (row0g < len) {
                float2 t = make_float2(o[db][0] * inv0, o[db][1] * inv0);
                *(float2*)(out + base + (size_t)row0g * Dc + db * 8 + colb) = t;
            }
            if (row1g < len) {
                float2 t = make_float2(o[db][2] * inv1, o[db][3] * inv1);
                *(float2*)(out + base + (size_t)row1g * Dc + db * 8 + colb) = t;
            }
        }
    }
}

// ---------------------------------------------------------------------------
extern "C" void kernel_launch(void* const* d_in, const int* in_sizes, int n_in,
                              void* d_out, int out_size)
{
    const float* q    = (const float*)d_in[0];
    const float* k    = (const float*)d_in[1];
    const float* v    = (const float*)d_in[2];
    const int*   lens = (const int*)d_in[5];
    float* out = (float*)d_out;

    (void)in_sizes; (void)n_in; (void)out_size;

    int prep_threads = Tc * 8 * 16;
    prep_kernel<<<(prep_threads + 255) / 256, 256>>>(q, k, v, lens);

    dim3 agrid(Sc / BM, Hc, Bc);
    attn_kernel<<<agrid, 128>>>(lens, out);
}